// round 16
// baseline (speedup 1.0000x reference)
#include <cuda_runtime.h>
#include <math.h>
#include <stdint.h>

// Problem constants
#define NQ 512
#define NC 65536
#define D  768
#define PD 64          // packed projection dim: e[0:32) h[32:48) s[48:64)

typedef unsigned long long u64;

// packed-fp32 helpers (sm_103 f32x2 — 2x FFMA throughput, exact fp32)
__device__ __forceinline__ u64 pack2(float v) {
    u64 r;
    asm("mov.b64 %0, {%1, %1};" : "=l"(r) : "f"(v));
    return r;
}
__device__ __forceinline__ void fma2(u64& d, u64 a, u64 b) {
    asm("fma.rn.f32x2 %0, %1, %2, %0;" : "+l"(d) : "l"(a), "l"(b));
}
__device__ __forceinline__ void unpack2(float& lo, float& hi, u64 v) {
    asm("mov.b64 {%0, %1}, %2;" : "=f"(lo), "=f"(hi) : "l"(v));
}

// fast acos: A&S 4.4.46-style 8-coeff, abs err ~2e-8, branch-free
__device__ __forceinline__ float facos(float x) {
    float ax = fabsf(x);
    float p = fmaf(ax, -0.0012624911f, 0.0066700901f);
    p = fmaf(p, ax, -0.0170881256f);
    p = fmaf(p, ax,  0.0308918810f);
    p = fmaf(p, ax, -0.0501743046f);
    p = fmaf(p, ax,  0.0889789874f);
    p = fmaf(p, ax, -0.2145988016f);
    p = fmaf(p, ax,  1.5707963050f);
    float r = sqrtf(1.0f - ax) * p;
    return (x >= 0.0f) ? r : (3.14159265358979f - r);
}

// hyperbolic: dd = 2*atanh(clamp(sqrt(nsq)/den, 0, 1-1e-7))
//           = ln((den+s)/(den-s)), s clamped — single divide
__device__ __forceinline__ float hyp_dd(float nsq, float den) {
    den = fmaxf(den, 1e-15f);
    float s = sqrtf(fmaxf(nsq, 0.0f));
    s = fminf(s, den * 0.9999999f);
    return __logf(__fdividef(den + s, den - s));
}

// Scratch (no allocations allowed)
__device__ float g_c[(size_t)NC * PD];   // corpus projections [row][64]
__device__ float g_cyn[NC];              // tanh^2(||h_lin||)
__device__ float g_q[(size_t)NQ * PD];
__device__ float g_qxn[NQ];
__device__ float g_qw[(size_t)NQ * 3];

// ---------------------------------------------------------------------------
// Kernel A: fused projection GEMM + weight-MLP.
// Blocks [0, 516): projection (R11 mainloop, R15 epilogue).
// Blocks [516, 1028): weight MLP, one block per query (R5 logic).
// ---------------------------------------------------------------------------
#define BK 32
#define ROWPAD 132
#define NCB128 (NC / 128)                 // 512
#define NQB128 (NQ / 128)                 // 4
#define PROJBLKS (NCB128 + NQB128)        // 516

#define XS_OFF  0
#define WS_OFF  (BK * ROWPAD)
#define OB_SZ   (128 * 68)
#define SRAW_FLOATS (OB_SZ > (BK*ROWPAD + BK*68) ? OB_SZ : (BK*ROWPAD + BK*68))

__global__ __launch_bounds__(256) void proj_kernel(
    const float* __restrict__ xc,
    const float* __restrict__ xq,
    const float* __restrict__ We, const float* __restrict__ be,
    const float* __restrict__ Wh, const float* __restrict__ bh,
    const float* __restrict__ Ws, const float* __restrict__ bs,
    const float* __restrict__ scale_h_p,
    const float* __restrict__ W1, const float* __restrict__ b1,
    const float* __restrict__ W2, const float* __restrict__ b2)
{
    __shared__ __align__(16) float sraw[SRAW_FLOATS];
    __shared__ float bias_s[64];

    const int tid = threadIdx.x;
    const int blk = blockIdx.x;

    // ------------------------- MLP path (blocks >= 516) ------------------
    if (blk >= PROJBLKS) {
        const int q    = blk - PROJBLKS;
        const int warp = tid >> 5, lane = tid & 31;
        float* xs  = sraw;            // [768]
        float* hid = sraw + D;        // [32]

        const float4* xrow4 = (const float4*)(xq + (size_t)q * D);
        if (tid < D / 4) ((float4*)xs)[tid] = xrow4[tid];
        __syncthreads();

        float acc0 = 0.f, acc1 = 0.f, acc2 = 0.f, acc3 = 0.f;
        const float* w0  = W1 + (size_t)(warp * 4 + 0) * D;
        const float* w1r = W1 + (size_t)(warp * 4 + 1) * D;
        const float* w2r = W1 + (size_t)(warp * 4 + 2) * D;
        const float* w3r = W1 + (size_t)(warp * 4 + 3) * D;
        #pragma unroll 4
        for (int k = lane; k < D; k += 32) {
            float xv = xs[k];
            acc0 = fmaf(w0[k],  xv, acc0);
            acc1 = fmaf(w1r[k], xv, acc1);
            acc2 = fmaf(w2r[k], xv, acc2);
            acc3 = fmaf(w3r[k], xv, acc3);
        }
        #pragma unroll
        for (int o = 16; o; o >>= 1) {
            acc0 += __shfl_xor_sync(0xffffffffu, acc0, o);
            acc1 += __shfl_xor_sync(0xffffffffu, acc1, o);
            acc2 += __shfl_xor_sync(0xffffffffu, acc2, o);
            acc3 += __shfl_xor_sync(0xffffffffu, acc3, o);
        }
        if (lane == 0) {
            hid[warp * 4 + 0] = fmaxf(acc0 + b1[warp * 4 + 0], 0.0f);
            hid[warp * 4 + 1] = fmaxf(acc1 + b1[warp * 4 + 1], 0.0f);
            hid[warp * 4 + 2] = fmaxf(acc2 + b1[warp * 4 + 2], 0.0f);
            hid[warp * 4 + 3] = fmaxf(acc3 + b1[warp * 4 + 3], 0.0f);
        }
        __syncthreads();

        if (warp == 0) {
            float h = hid[lane];
            #pragma unroll
            for (int i = 0; i < 3; i++) {
                float p = h * W2[i * 32 + lane];
                #pragma unroll
                for (int o = 16; o; o >>= 1) p += __shfl_xor_sync(0xffffffffu, p, o);
                if (lane == 0) {
                    float z  = p + b2[i];
                    float sp = fmaxf(z, 0.0f) + log1pf(expf(-fabsf(z)));
                    g_qw[(size_t)q * 3 + i] = sp;
                }
            }
        }
        return;
    }

    // ------------------------- projection path ---------------------------
    float* xs  = sraw + XS_OFF;
    float* wsm = sraw + WS_OFF;
    float* ob  = sraw;

    const bool isQ  = (blk >= NCB128);
    const int  row0 = isQ ? (blk - NCB128) * 128 : blk * 128;
    const float* xsrc = isQ ? xq : xc;
    float* gout = isQ ? g_q  : g_c;
    float* gyn  = isQ ? g_qxn : g_cyn;

    if (tid < 64) {
        float b;
        if (tid < 32)      b = be[tid];
        else if (tid < 48) b = bh[tid - 32];
        else               b = bs[tid - 48];
        bias_s[tid] = b;
    }

    const float* wrow_base[2];
    {
        int n0 = (tid + 0 * 256) >> 3;
        int n1 = (tid + 1 * 256) >> 3;
        wrow_base[0] = (n0 < 32) ? We + (size_t)n0 * D
                      : (n0 < 48) ? Wh + (size_t)(n0 - 32) * D
                                  : Ws + (size_t)(n0 - 48) * D;
        wrow_base[1] = (n1 < 32) ? We + (size_t)n1 * D
                      : (n1 < 48) ? Wh + (size_t)(n1 - 32) * D
                                  : Ws + (size_t)(n1 - 48) * D;
    }

    const int tr = (tid >> 4) * 8;
    const int tc = (tid & 15) * 4;

    u64 acc[8][2] = {};
    const float* xbase = xsrc + (size_t)row0 * D;

    for (int kk = 0; kk < D; kk += BK) {
        float4 xv[4], wv[2];
        #pragma unroll
        for (int i = 0; i < 4; i++) {
            int idx = tid + i * 256;
            int r   = idx >> 3;
            int k4  = (idx & 7) * 4;
            xv[i] = *(const float4*)(xbase + (size_t)r * D + kk + k4);
        }
        #pragma unroll
        for (int i = 0; i < 2; i++) {
            int idx = tid + i * 256;
            int k4  = (idx & 7) * 4;
            wv[i] = *(const float4*)(wrow_base[i] + kk + k4);
        }
        __syncthreads();
        #pragma unroll
        for (int i = 0; i < 4; i++) {
            int idx = tid + i * 256;
            int r   = idx >> 3;
            int k4  = (idx & 7) * 4;
            xs[(k4 + 0) * ROWPAD + r] = xv[i].x;
            xs[(k4 + 1) * ROWPAD + r] = xv[i].y;
            xs[(k4 + 2) * ROWPAD + r] = xv[i].z;
            xs[(k4 + 3) * ROWPAD + r] = xv[i].w;
        }
        #pragma unroll
        for (int i = 0; i < 2; i++) {
            int idx = tid + i * 256;
            int n   = idx >> 3;
            int k4  = (idx & 7) * 4;
            wsm[(k4 + 0) * 68 + n] = wv[i].x;
            wsm[(k4 + 1) * 68 + n] = wv[i].y;
            wsm[(k4 + 2) * 68 + n] = wv[i].z;
            wsm[(k4 + 3) * 68 + n] = wv[i].w;
        }
        __syncthreads();

        #pragma unroll
        for (int k = 0; k < BK; k++) {
            float4 a0 = *(const float4*)&xs[k * ROWPAD + tr];
            float4 a1 = *(const float4*)&xs[k * ROWPAD + tr + 4];
            ulonglong2 b = *(const ulonglong2*)&wsm[k * 68 + tc];
            u64 ap[8];
            ap[0] = pack2(a0.x); ap[1] = pack2(a0.y);
            ap[2] = pack2(a0.z); ap[3] = pack2(a0.w);
            ap[4] = pack2(a1.x); ap[5] = pack2(a1.y);
            ap[6] = pack2(a1.z); ap[7] = pack2(a1.w);
            #pragma unroll
            for (int i = 0; i < 8; i++) {
                fma2(acc[i][0], ap[i], b.x);
                fma2(acc[i][1], ap[i], b.y);
            }
        }
        __syncthreads();
    }

    #pragma unroll
    for (int i = 0; i < 8; i++) {
        float v0, v1, v2, v3;
        unpack2(v0, v1, acc[i][0]);
        unpack2(v2, v3, acc[i][1]);
        float4 w4 = {v0, v1, v2, v3};
        *(float4*)&ob[(tr + i) * 68 + tc] = w4;
    }
    __syncthreads();

    const float sc = *scale_h_p;
    #pragma unroll
    for (int it = 0; it < 2; it++) {
        const int r    = (tid >> 2) + it * 64;
        const int part = tid & 3;
        const int cbase = part * 16;
        float vals[16];
        float ss = 0.0f;
        #pragma unroll
        for (int j = 0; j < 16; j++) {
            float v = ob[r * 68 + cbase + j] + bias_s[cbase + j];
            if (part == 2) v *= sc;
            vals[j] = v;
            ss += v * v;
        }
        float other = __shfl_xor_sync(0xffffffffu, ss, 1);
        float seg   = (part < 2) ? (ss + other) : ss;

        const int grow = row0 + r;
        float* orow = gout + (size_t)grow * PD + cbase;
        if (part == 2) {
            float n  = fmaxf(sqrtf(seg), 1e-15f);
            float ex = __expf(2.0f * n);
            float th = 1.0f - 2.0f / (ex + 1.0f);
            float f  = th / n;
            #pragma unroll
            for (int j = 0; j < 16; j++) orow[j] = vals[j] * f;
            gyn[grow] = th * th;
        } else {
            float inv = rsqrtf(seg);
            #pragma unroll
            for (int j = 0; j < 16; j++) orow[j] = vals[j] * inv;
        }
    }
}

// ---------------------------------------------------------------------------
// Kernel B: pairwise.  R15 epilogue EXACTLY; mainloop uses duplicated q-tile
// (qs2[k][2q]=[2q+1]=v) so a-operands are pre-packed u64 pairs via LDS.128 —
// deletes the 4 pack2/k.  52KB dynamic smem (occupancy unchanged: reg-limited).
// ---------------------------------------------------------------------------
#define QP2      132   // duplicated q row pitch (floats)
#define PW_QS2   0
#define PW_CS    (64 * QP2)
#define PW_SQXN  (PW_CS + 64 * 68)
#define PW_SQW   (PW_SQXN + 64)
#define PW_SCYN  (PW_SQW + 64 * 3)
#define PW_FLOATS (PW_SCYN + 64)
#define PW_SMEM  (PW_FLOATS * 4)

__global__ __launch_bounds__(256) void pairwise_kernel(float* __restrict__ out)
{
    extern __shared__ __align__(16) float psm[];
    float* qs2  = psm + PW_QS2;
    float* cs   = psm + PW_CS;
    float* sqxn = psm + PW_SQXN;
    float* sqw  = psm + PW_SQW;
    float* scyn = psm + PW_SCYN;

    const int tid   = threadIdx.x;
    const int c0blk = blockIdx.x * 64;
    const int q0blk = blockIdx.y * 64;

    #pragma unroll
    for (int i = 0; i < 4; i++) {
        int f4  = tid + i * 256;
        int row = f4 >> 4;
        int k4  = (f4 & 15) * 4;
        float4 v = *(const float4*)(g_q + (size_t)(q0blk + row) * PD + k4);
        float* q0 = qs2 + (k4 + 0) * QP2 + 2 * row;
        float* q1 = qs2 + (k4 + 1) * QP2 + 2 * row;
        float* q2 = qs2 + (k4 + 2) * QP2 + 2 * row;
        float* q3 = qs2 + (k4 + 3) * QP2 + 2 * row;
        q0[0] = v.x; q0[1] = v.x;
        q1[0] = v.y; q1[1] = v.y;
        q2[0] = v.z; q2[1] = v.z;
        q3[0] = v.w; q3[1] = v.w;
        float4 w = *(const float4*)(g_c + (size_t)(c0blk + row) * PD + k4);
        cs[(k4 + 0) * 68 + row] = w.x;
        cs[(k4 + 1) * 68 + row] = w.y;
        cs[(k4 + 2) * 68 + row] = w.z;
        cs[(k4 + 3) * 68 + row] = w.w;
    }
    if (tid < 64) {
        sqxn[tid]        = g_qxn[q0blk + tid];
        scyn[tid]        = g_cyn[c0blk + tid];
        sqw[tid * 3 + 0] = g_qw[(size_t)(q0blk + tid) * 3 + 0];
        sqw[tid * 3 + 1] = g_qw[(size_t)(q0blk + tid) * 3 + 1];
        sqw[tid * 3 + 2] = g_qw[(size_t)(q0blk + tid) * 3 + 2];
    }
    __syncthreads();

    const int tq0 = (tid >> 4) * 4;
    const int tc0 = (tid & 15) * 4;

    u64 ae[4][2] = {}, ah[4][2] = {}, as2[4][2] = {};

    #pragma unroll
    for (int k = 0; k < 32; k++) {
        const float* qk = qs2 + k * QP2 + 2 * tq0;
        ulonglong2 a01 = *(const ulonglong2*)(qk);
        ulonglong2 a23 = *(const ulonglong2*)(qk + 4);
        ulonglong2 b = *(const ulonglong2*)&cs[k * 68 + tc0];
        fma2(ae[0][0], a01.x, b.x); fma2(ae[0][1], a01.x, b.y);
        fma2(ae[1][0], a01.y, b.x); fma2(ae[1][1], a01.y, b.y);
        fma2(ae[2][0], a23.x, b.x); fma2(ae[2][1], a23.x, b.y);
        fma2(ae[3][0], a23.y, b.x); fma2(ae[3][1], a23.y, b.y);
    }
    #pragma unroll
    for (int k = 32; k < 48; k++) {
        const float* qk = qs2 + k * QP2 + 2 * tq0;
        ulonglong2 a01 = *(const ulonglong2*)(qk);
        ulonglong2 a23 = *(const ulonglong2*)(qk + 4);
        ulonglong2 b = *(const ulonglong2*)&cs[k * 68 + tc0];
        fma2(ah[0][0], a01.x, b.x); fma2(ah[0][1], a01.x, b.y);
        fma2(ah[1][0], a01.y, b.x); fma2(ah[1][1], a01.y, b.y);
        fma2(ah[2][0], a23.x, b.x); fma2(ah[2][1], a23.x, b.y);
        fma2(ah[3][0], a23.y, b.x); fma2(ah[3][1], a23.y, b.y);
    }
    #pragma unroll
    for (int k = 48; k < 64; k++) {
        const float* qk = qs2 + k * QP2 + 2 * tq0;
        ulonglong2 a01 = *(const ulonglong2*)(qk);
        ulonglong2 a23 = *(const ulonglong2*)(qk + 4);
        ulonglong2 b = *(const ulonglong2*)&cs[k * 68 + tc0];
        fma2(as2[0][0], a01.x, b.x); fma2(as2[0][1], a01.x, b.y);
        fma2(as2[1][0], a01.y, b.x); fma2(as2[1][1], a01.y, b.y);
        fma2(as2[2][0], a23.x, b.x); fma2(as2[2][1], a23.x, b.y);
        fma2(as2[3][0], a23.y, b.x); fma2(as2[3][1], a23.y, b.y);
    }

    #pragma unroll
    for (int i = 0; i < 4; i++) {
        const int q    = tq0 + i;
        const float xn = sqxn[q];
        const float w0 = sqw[q * 3 + 0], w1 = sqw[q * 3 + 1], w2 = sqw[q * 3 + 2];
        const float beta = 1.0f - xn;
        const float tw0  = 2.0f * w0;

        float ev[4], hv[4], sv[4];
        unpack2(ev[0], ev[1], ae[i][0]);  unpack2(ev[2], ev[3], ae[i][1]);
        unpack2(hv[0], hv[1], ah[i][0]);  unpack2(hv[2], hv[3], ah[i][1]);
        unpack2(sv[0], sv[1], as2[i][0]); unpack2(sv[2], sv[3], as2[i][1]);

        float rv[4];
        #pragma unroll
        for (int j = 0; j < 4; j++) {
            const float yn = scyn[tc0 + j];
            float dots = fminf(fmaxf(sv[j], -0.9999999f), 0.9999999f);
            float acs  = facos(dots);
            float ds   = acs * acs;
            float dt    = hv[j];
            float alpha = 1.0f - 2.0f * dt + yn;
            float nsq   = alpha*alpha*xn - 2.0f*alpha*beta*dt + beta*beta*yn;
            float den   = 1.0f - 2.0f*dt + xn*yn;
            float dd    = hyp_dd(nsq, den);
            float dh    = dd * dd;
            float acc = fmaf(w1, dh, fmaf(w2, ds, tw0));
            rv[j] = fmaf(tw0, ev[j], -acc);
        }
        float4 res = {rv[0], rv[1], rv[2], rv[3]};
        *(float4*)(out + (size_t)(q0blk + q) * NC + c0blk + tc0) = res;
    }
}

// ---------------------------------------------------------------------------
extern "C" void kernel_launch(void* const* d_in, const int* in_sizes, int n_in,
                              void* d_out, int out_size)
{
    const float* xq  = (const float*)d_in[0];
    const float* xc  = (const float*)d_in[1];
    const float* We  = (const float*)d_in[2];
    const float* be  = (const float*)d_in[3];
    const float* Wh  = (const float*)d_in[4];
    const float* bh  = (const float*)d_in[5];
    const float* Ws  = (const float*)d_in[6];
    const float* bs  = (const float*)d_in[7];
    const float* sh  = (const float*)d_in[8];
    const float* W1  = (const float*)d_in[9];
    const float* b1  = (const float*)d_in[10];
    const float* W2  = (const float*)d_in[11];
    const float* b2  = (const float*)d_in[12];
    float* out = (float*)d_out;

    // Unconditional, idempotent (no static guards allowed).
    cudaFuncSetAttribute(pairwise_kernel,
                         cudaFuncAttributeMaxDynamicSharedMemorySize, PW_SMEM);

    proj_kernel<<<PROJBLKS + NQ, 256>>>(xc, xq, We, be, Wh, bh, Ws, bs, sh,
                                        W1, b1, W2, b2);
    pairwise_kernel<<<dim3(NC / 64, NQ / 64), 256, PW_SMEM>>>(out);
}